// round 8
// baseline (speedup 1.0000x reference)
#include <cuda_runtime.h>
#include <cuda_bf16.h>
#include <cstdint>

// NonSparsePLIF: v[t] = where(v[t-1]*d + x[t] >= 1.0, 0, v[t-1]*d + x[t])
// x_seq [T=16, 4194304] f32, decay [1] f32. HBM-bound streaming scan.
// R8: 256-bit global accesses (sm_100+ ld/st.global.v8.f32) — 8 floats per
// thread per timestep. Halves LSU instruction count, maximizes bytes per
// L1tex wavefront. All 128-bit variants measured flat at 76.4-77.6us.

#define T_STEPS 16
#define SPATIAL 4194304            // 16*64*64*64
#define SPATIAL8 (SPATIAL / 8)     // 524288 float8 slots per timestep plane
#define THREADS 256
#define VTH 1.0f

struct __align__(32) f8 { float v[8]; };

__device__ __forceinline__ f8 ldg256(const f8* p) {
    f8 r;
    asm volatile("ld.global.v8.f32 {%0,%1,%2,%3,%4,%5,%6,%7}, [%8];"
        : "=f"(r.v[0]), "=f"(r.v[1]), "=f"(r.v[2]), "=f"(r.v[3]),
          "=f"(r.v[4]), "=f"(r.v[5]), "=f"(r.v[6]), "=f"(r.v[7])
        : "l"(p));
    return r;
}

__device__ __forceinline__ void stg256_cs(f8* p, const f8& r) {
    asm volatile("st.global.cs.v8.f32 [%0], {%1,%2,%3,%4,%5,%6,%7,%8};"
        :: "l"(p),
           "f"(r.v[0]), "f"(r.v[1]), "f"(r.v[2]), "f"(r.v[3]),
           "f"(r.v[4]), "f"(r.v[5]), "f"(r.v[6]), "f"(r.v[7])
        : "memory");
}

__global__ __launch_bounds__(THREADS) void plif_kernel(
    const f8* __restrict__ x,          // [T, SPATIAL8]
    const float* __restrict__ decay,   // [1]
    f8* __restrict__ out)              // [T, SPATIAL8]
{
    const int i = blockIdx.x * THREADS + threadIdx.x;
    if (i >= SPATIAL8) return;

    const float d = decay[0];

    float v[8];
#pragma unroll
    for (int k = 0; k < 8; ++k) v[k] = 0.f;

#pragma unroll
    for (int t = 0; t < T_STEPS; ++t) {
        const size_t idx = (size_t)t * SPATIAL8 + i;
        const f8 xt = ldg256(&x[idx]);
        f8 o;
#pragma unroll
        for (int k = 0; k < 8; ++k) {
            float nv = fmaf(v[k], d, xt.v[k]);
            nv = (nv >= VTH) ? 0.f : nv;
            v[k] = nv;
            o.v[k] = nv;
        }
        stg256_cs(&out[idx], o);
    }
}

extern "C" void kernel_launch(void* const* d_in, const int* in_sizes, int n_in,
                              void* d_out, int out_size)
{
    const f8*    x   = (const f8*)d_in[0];
    const float* dec = (const float*)d_in[1];
    f8*          out = (f8*)d_out;

    const int blocks = (SPATIAL8 + THREADS - 1) / THREADS;  // 2048
    plif_kernel<<<blocks, THREADS>>>(x, dec, out);
}

// round 9
// speedup vs baseline: 1.0244x; 1.0244x over previous
#include <cuda_runtime.h>
#include <cuda_bf16.h>

// NonSparsePLIF: v[t] = where(v[t-1]*d + x[t] >= 1.0, 0, v[t-1]*d + x[t])
// x_seq [T=16, 4194304] f32, decay [1] f32.
//
// FINAL — best of 8 measured variants (R4/R7, reproduced twice):
//   1 float4 per thread, block=256, grid=4096, plain loads, __stcs stores.
//   76.4-77.0us kernel, DRAM ~79.5% (6.3 TB/s). Roofline: 512 MB mandatory
//   1:1 read/write traffic at the path-independent LTS/HBM cap. Measured flat
//   or worse: 2xMLP, ldcs, persistent grid, block=128, 2-step bursts, 256-bit
//   v8 accesses. No reuse/fusion/precision lever exists for this problem.

#define T_STEPS 16
#define SPATIAL 4194304            // 16*64*64*64
#define SPATIAL4 (SPATIAL / 4)     // float4 elements per timestep plane
#define VTH 1.0f

__global__ __launch_bounds__(256) void plif_kernel(
    const float4* __restrict__ x,      // [T, SPATIAL4]
    const float* __restrict__ decay,   // [1]
    float4* __restrict__ out)          // [T, SPATIAL4]
{
    const int i = blockIdx.x * blockDim.x + threadIdx.x;
    if (i >= SPATIAL4) return;

    const float d = decay[0];

    float4 v = make_float4(0.f, 0.f, 0.f, 0.f);

#pragma unroll
    for (int t = 0; t < T_STEPS; ++t) {
        const size_t idx = (size_t)t * SPATIAL4 + i;
        const float4 xt = x[idx];
        v.x = fmaf(v.x, d, xt.x);
        v.y = fmaf(v.y, d, xt.y);
        v.z = fmaf(v.z, d, xt.z);
        v.w = fmaf(v.w, d, xt.w);
        v.x = (v.x >= VTH) ? 0.f : v.x;
        v.y = (v.y >= VTH) ? 0.f : v.y;
        v.z = (v.z >= VTH) ? 0.f : v.z;
        v.w = (v.w >= VTH) ? 0.f : v.w;
        __stcs(&out[idx], v);   // write-once output: evict-first in L2
    }
}

extern "C" void kernel_launch(void* const* d_in, const int* in_sizes, int n_in,
                              void* d_out, int out_size)
{
    const float4* x   = (const float4*)d_in[0];
    const float*  dec = (const float*)d_in[1];
    float4*       out = (float4*)d_out;

    const int threads = 256;
    const int blocks  = (SPATIAL4 + threads - 1) / threads;  // 4096
    plif_kernel<<<blocks, threads>>>(x, dec, out);
}